// round 15
// baseline (speedup 1.0000x reference)
#include <cuda_runtime.h>
#include <cuda_bf16.h>
#include <cstdint>

#define D_MODEL 2048
#define RANK    64
#define VOCAB   50257
#define N_TOK   32

#define NPART   32

__device__ float g_part[NPART * N_TOK];
__device__ float g_s[N_TOK];
__device__ int   g_count;              // self-resetting

// Kernel 1: s[n] = sum_d h[n,d]*(sum_r U[d,r]*S[r]); 32 blocks, last folds.
__global__ __launch_bounds__(256)
void fftlm_s_kernel(const float* __restrict__ h,
                    const float* __restrict__ U,
                    const float* __restrict__ S) {
    __shared__ float sS[RANK];
    __shared__ float su[64];
    __shared__ int   is_last;
    const int tid = threadIdx.x;
    const int warp = tid >> 5, lane = tid & 31;
    const int dbase = blockIdx.x * 64;

    if (tid < RANK) sS[tid] = S[tid];
    __syncthreads();
#pragma unroll
    for (int k = 0; k < 8; k++) {
        int dl = warp * 8 + k;
        const float* Ur = U + (size_t)(dbase + dl) * RANK;
        float v = Ur[lane] * sS[lane] + Ur[lane + 32] * sS[lane + 32];
#pragma unroll
        for (int o = 16; o; o >>= 1) v += __shfl_xor_sync(0xffffffffu, v, o);
        if (lane == 0) su[dl] = v;
    }
    __syncthreads();
#pragma unroll
    for (int k = 0; k < 4; k++) {
        int n = warp * 4 + k;
        const float* hr = h + (size_t)n * D_MODEL + dbase;
        float v = hr[lane] * su[lane] + hr[lane + 32] * su[lane + 32];
#pragma unroll
        for (int o = 16; o; o >>= 1) v += __shfl_xor_sync(0xffffffffu, v, o);
        if (lane == 0) g_part[blockIdx.x * N_TOK + n] = v;
    }
    __threadfence();
    if (tid == 0) is_last = (atomicAdd(&g_count, 1) == NPART - 1);
    __syncthreads();
    if (is_last) {
        if (tid < N_TOK) {
            float acc = 0.f;
#pragma unroll
            for (int b = 0; b < NPART; b++) acc += g_part[b * N_TOK + tid];
            g_s[tid] = acc;
        }
        if (tid == 0) g_count = 0;   // self-reset for graph replay
    }
}

// Kernel 2 (the whole job): out[n,v] = s[n] * sum_r Vh[r,v].
// 1 thread/column, 64-row sum with two 16-deep double-buffered load batches
// (16-32 lines in flight per warp), then 32 broadcast stores straight to out.
// __launch_bounds__(128,8): 64-reg budget -> both buffers stay live.
__global__ __launch_bounds__(128, 8)
void fftlm_main_kernel(const float* __restrict__ Vh,
                       float* __restrict__ out) {
    __shared__ float s_sh[N_TOK];
    const int tid = threadIdx.x;
    if (tid < N_TOK) s_sh[tid] = g_s[tid];   // ready: kernel 1 ordered before us
    __syncthreads();

    const int col = blockIdx.x * 128 + tid;
    if (col >= VOCAB) return;

    const float* p0 = Vh + col;                       // rows  0..31
    const float* p1 = Vh + (size_t)32 * VOCAB + col;  // rows 32..63

    float b0[16], b1[16];
    // batch 1+2 in flight together
#pragma unroll
    for (int i = 0; i < 16; i++) b0[i] = p0[(size_t)i * VOCAB];
#pragma unroll
    for (int i = 0; i < 16; i++) b1[i] = p0[(size_t)(16 + i) * VOCAB];

    // consume b0 (tree), refill with rows 32..47 — keeps >=16 in flight
#pragma unroll
    for (int s2 = 8; s2 >= 1; s2 >>= 1)
#pragma unroll
        for (int i = 0; i < s2; i++) b0[i] += b0[i + s2];
    const float acc0 = b0[0];
#pragma unroll
    for (int i = 0; i < 16; i++) b0[i] = p1[(size_t)i * VOCAB];

#pragma unroll
    for (int s2 = 8; s2 >= 1; s2 >>= 1)
#pragma unroll
        for (int i = 0; i < s2; i++) b1[i] += b1[i + s2];
    const float acc1 = b1[0];
#pragma unroll
    for (int i = 0; i < 16; i++) b1[i] = p1[(size_t)(16 + i) * VOCAB];

#pragma unroll
    for (int s2 = 8; s2 >= 1; s2 >>= 1)
#pragma unroll
        for (int i = 0; i < s2; i++) b0[i] += b0[i + s2];
#pragma unroll
    for (int s2 = 8; s2 >= 1; s2 >>= 1)
#pragma unroll
        for (int i = 0; i < s2; i++) b1[i] += b1[i + s2];

    const float w = (acc0 + acc1) + (b0[0] + b1[0]);

    float* q = out + col;
#pragma unroll
    for (int n = 0; n < N_TOK; n++)
        q[(size_t)n * VOCAB] = s_sh[n] * w;
}

extern "C" void kernel_launch(void* const* d_in, const int* in_sizes, int n_in,
                              void* d_out, int out_size) {
    const float* h  = (const float*)d_in[0];  // (32, 2048)
    const float* U  = (const float*)d_in[1];  // (2048, 64)
    const float* S  = (const float*)d_in[2];  // (64,)
    const float* Vh = (const float*)d_in[3];  // (64, 50257)
    float* out = (float*)d_out;               // (32, 50257)

    fftlm_s_kernel<<<NPART, 256>>>(h, U, S);

    const int blocks = (VOCAB + 127) / 128;   // 393
    fftlm_main_kernel<<<blocks, 128>>>(Vh, out);
}